// round 13
// baseline (speedup 1.0000x reference)
#include <cuda_runtime.h>

#define T_LEN   2048
#define CSTEP   16                      // timesteps per chunk
#define NCHUNK  (T_LEN / CSTEP)         // 128
#define NITER   (NCHUNK + 4)            // 5-deep pipeline: L->A->B->C->D
#define NGRP_C  (CSTEP / 4)             // float4-groups per chunk (4)

// MUFU tanh: ~100 cyc latency on sm_100a (measured across rounds). Used only
// OFF the carried state cycles, where latency pipelines across steps.
__device__ __forceinline__ float tanh_fast(float x) {
    float y;
    asm("tanh.approx.f32 %0, %1;" : "=f"(y) : "f"(x));
    return y;
}

// FMA/ALU-pipe tanh for the carried chains (no MUFU -> ~68 cyc dep chain):
//   tanh(a) = sign(a) * (1 - 2u/(1+u)),  u = e^{-2|a|} = 2^z, z = -2.885*|a|
// exp2 by magic-round (+1.5*2^23) + deg-5 Taylor on f in [-0.5,0.5] + integer
// exponent reconstruction; 1/(1+u) by linear seed + 2 Newton (d in [1,2]).
// Abs err <= ~1.5e-5; exact saturation for |a| large (z clamped at -28).
__device__ __forceinline__ float tanh_chain(float a) {
    const float sa = copysignf(1.0f, a);
    const float ab = fabsf(a);
    const float z  = fmaxf(-2.88539008f * ab, -28.0f);
    const float tm = z + 12582912.0f;            // round-to-nearest int
    const float nf = tm - 12582912.0f;
    const float fr = z - nf;                     // [-0.5, 0.5]
    const int   sb = (__float_as_int(tm) + (127 - 0x4B400000)) << 23;
    const float scale = __int_as_float(sb);      // 2^n
    const float f2  = fr * fr;
    const float A01 = fmaf(0.693147181f,   fr, 1.0f);
    const float B23 = fmaf(0.0555041087f,  fr, 0.240226507f);
    const float C45 = fmaf(0.00133335581f, fr, 0.00961812911f);
    const float p   = fmaf(f2, fmaf(f2, C45, B23), A01);   // 2^fr
    const float u   = p * scale;                 // e^{-2|a|} in (0, 1]
    const float d   = 1.0f + u;                  // [1, 2]
    float x = fmaf(-1.88235294f, d, 2.82352941f);   // 48/17 - 32/17*d
    x = x * fmaf(-d, x, 2.0f);                   // Newton 1
    x = x * fmaf(-d, x, 2.0f);                   // Newton 2: rel ~1.2e-5
    const float w = (sa * u) * -2.0f;            // -2*sign*u (off chain-end)
    return fmaf(w, x, sa);                       // sign*(1 - 2u/(1+u))
}

// State in the x10 domain (WU = 10*wu etc); clips at +-1e5 are exact no-ops.
//
// 5-warp pipeline, one chunk skew per stage, one __syncthreads per iter:
//   warp4 (L): STS chunk k inputs, LDG chunk k+1
//   warp0 (A): WU chain, chunk k-1  (chain tanh t1 = FMA-pipe; tr = MUFU)
//   warp1 (B): WL chain, chunk k-2  (chain tanh t2 = FMA-pipe; t3 = MUFU)
//   warp2 (C): WD chain, chunk k-3  (chain tanh t4 = FMA-pipe; t5 = MUFU)
//   warp3 (D): runoff/q + stores, chunk k-4 (tq = MUFU, stateless)
__global__ void __launch_bounds__(160, 1) xaj_kernel(
    const float* __restrict__ inputs,
    const float* __restrict__ pwum, const float* __restrict__ pwlm,
    const float* __restrict__ pwdm, const float* __restrict__ pc,
    const float* __restrict__ pb,  const float* __restrict__ pk1,
    const float* __restrict__ pk2, const float* __restrict__ pk3,
    float* __restrict__ out, int B)
{
    __shared__ float2 sPP[2][CSTEP][32];   // (pet10, p10)  L -> A
    __shared__ float2 sRD[2][CSTEP][32];   // (REM, D1)     A -> B
    __shared__ float2 sXD[2][CSTEP][32];   // (X, D2)       B -> C
    __shared__ float  sWD[2][CSTEP][32];   // WDn           C -> D
    __shared__ float  sCT[4][CSTEP][32];   // ct2           A -> D (distance 3)

    const int lane = threadIdx.x & 31;
    const int wid  = threadIdx.x >> 5;
    const int row  = blockIdx.x * 32 + lane;

    // scalar params (reference arg swap: runoff_production(wu, wd, wl, p,
    // wum, wdm, wlm, b, c))
    const float wum_p = pwum[0] * 19.9f + 0.1f;
    const float wlm_p = pwdm[0] * 30.0f + 60.0f;
    const float wdm_p = pwlm[0] * 60.0f + 60.0f;
    const float W      = wum_p + wlm_p + wdm_p;
    const float invW10 = 0.1f / W;           // x10-state -> w/W
    const float negc2  = -(pc[0] * 0.19f + 0.01f);
    const float negb2  = -(pb[0] * 0.30f + 0.10f);
    const float k1 = pk1[0] * 0.69f + 0.01f;
    const float k2 = pk2[0] * 0.69f + 0.01f;
    const float k3 = pk3[0] * 0.89f + 0.01f;
    const float F  = k1 + 0.5f * k2 * (1.0f - k1)
                   + 0.25f * k3 * (1.0f - k2) * (1.0f - k1);
    const float halfF = 0.5f * F;

    const float4* __restrict__ in4 =
        reinterpret_cast<const float4*>(inputs + (size_t)row * (T_LEN * 3));
    float4* __restrict__ out4 =
        reinterpret_cast<float4*>(out + (size_t)row * T_LEN);

    float WU = 0.0f, WL = 0.0f, WD = 0.0f;

    // loader's in-flight chunk registers (chunk to be STS'd this iteration)
    float4 f[NGRP_C][3];
    if (wid == 4) {
        #pragma unroll
        for (int j = 0; j < NGRP_C; ++j) {
            f[j][0] = in4[j * 3 + 0];
            f[j][1] = in4[j * 3 + 1];
            f[j][2] = in4[j * 3 + 2];
        }
    }

    for (int k = 0; k < NITER; ++k) {
        if (wid == 4) {
            // ---- loader: STS chunk k, then issue LDGs for chunk k+1 ----
            if (k < NCHUNK) {
                const int slot = k & 1;
                #pragma unroll
                for (int j = 0; j < NGRP_C; ++j) {
                    // (B,T,3): pet = ch0, p = ch2
                    const float pet_[4] = { f[j][0].x, f[j][0].w,
                                            f[j][1].z, f[j][2].y };
                    const float pr_ [4] = { f[j][0].z, f[j][1].y,
                                            f[j][2].x, f[j][2].w };
                    #pragma unroll
                    for (int i = 0; i < 4; ++i)
                        sPP[slot][j * 4 + i][lane] =
                            make_float2(10.0f * pet_[i], 10.0f * pr_[i]);
                }
                if (k + 1 < NCHUNK) {
                    #pragma unroll
                    for (int j = 0; j < NGRP_C; ++j) {
                        const int g = (k + 1) * NGRP_C + j;
                        f[j][0] = in4[g * 3 + 0];
                        f[j][1] = in4[g * 3 + 1];
                        f[j][2] = in4[g * 3 + 2];
                    }
                }
            }
        } else if (wid == 0) {
            // ---- stage A: WU chain, chunk k-1 ----
            if (k >= 1 && k <= NCHUNK) {
                const int ka = k - 1, slot = ka & 1, cslot = ka & 3;
                #pragma unroll 4
                for (int t = 0; t < CSTEP; ++t) {
                    const float2 pp   = sPP[slot][t][lane];
                    const float pet10 = pp.x;
                    const float p10   = pp.y;
                    const float a    = WU - pet10;
                    const float ha   = 0.5f * a;
                    const float ct   = fmaf(-0.5f, pet10, p10);
                    const float base = fmaf(0.5f, WU, ct);
                    const float sum  = WU + p10;
                    const float t1   = tanh_chain(a);        // FMA-pipe chain
                    const float WUn  = fmaf(t1, ha, base);   // carried cycle
                    const float ET1  = sum - WUn;            // off-chain
                    const float Z    = pet10 - ET1;
                    const float tr   = tanh_fast(Z);         // MUFU, off-chain
                    const float hZ   = 0.5f * Z;
                    const float REM  = fmaf(tr, hZ, hZ);
                    const float D1   = p10 - ET1;
                    const float u    = WUn * invW10;         // wu/W (new state)
                    const float cu   = negc2 * u;
                    const float praw = 0.1f * p10;
                    const float ct2  = fmaf(cu, u, praw);    // p - c2*u^2
                    sRD[slot][t][lane]  = make_float2(REM, D1);
                    sCT[cslot][t][lane] = ct2;
                    WU = WUn;
                }
            }
        } else if (wid == 1) {
            // ---- stage B: WL chain, chunk k-2 ----
            if (k >= 2 && k <= NCHUNK + 1) {
                const int kb = k - 2, slot = kb & 1;
                #pragma unroll 4
                for (int t = 0; t < CSTEP; ++t) {
                    const float2 rd  = sRD[slot][t][lane];
                    const float REM  = rd.x;
                    const float D1   = rd.y;
                    const float t3   = tanh_fast(REM);       // MUFU, off-chain
                    const float g3   = fmaf(t3,  0.5f,  0.5f);
                    const float ng3  = fmaf(t3, -0.5f, -0.5f);
                    const float aB   = REM - WL;
                    const float t2   = tanh_chain(aB);       // FMA-pipe chain
                    const float hB   = -0.5f * aB;           // 0.5(WL-REM)
                    const float mB   = fmaf(0.5f, WL, 0.5f * REM);
                    const float ET22 = fmaf(t2, hB, mB);     // carried cycle
                    const float ET2  = g3 * ET22;
                    const float WLD  = WL + D1;
                    WL = fmaf(ng3, ET22, WLD);               // WL + D1 - ET2
                    sXD[slot][t][lane] =
                        make_float2(REM - ET2, D1 - ET2);    // (X, D2)
                }
            }
        } else if (wid == 2) {
            // ---- stage C: WD chain, chunk k-3 ----
            if (k >= 3 && k <= NCHUNK + 2) {
                const int kc = k - 3, slot = kc & 1;
                #pragma unroll 4
                for (int t = 0; t < CSTEP; ++t) {
                    const float2 xd  = sXD[slot][t][lane];
                    const float X    = xd.x;
                    const float D2   = xd.y;
                    const float t5   = tanh_fast(X);         // MUFU, off-chain
                    const float ng5  = fmaf(t5, -0.5f, -0.5f);
                    const float aC   = X - WD;
                    const float t4   = tanh_chain(aC);       // FMA-pipe chain
                    const float hC   = -0.5f * aC;           // 0.5(WD-X)
                    const float mC   = fmaf(0.5f, WD, 0.5f * X);
                    const float ET33 = fmaf(t4, hC, mC);     // carried cycle
                    const float WDD  = WD + D2;
                    const float WDn  = fmaf(ng5, ET33, WDD); // WD + D2 - ET3
                    sWD[slot][t][lane] = WDn;
                    WD = WDn;
                }
            }
        } else if (wid == 3) {
            // ---- stage D: runoff/q + stores, chunk k-4 (stateless) ----
            if (k >= 4) {
                const int kd = k - 4, slot = kd & 1, cslot = kd & 3;
                #pragma unroll
                for (int j = 0; j < NGRP_C; ++j) {
                    float qv[4];
                    #pragma unroll
                    for (int i = 0; i < 4; ++i) {
                        const int   t   = j * 4 + i;
                        const float WDn = sWD[slot][t][lane];
                        const float ct2 = sCT[cslot][t][lane];
                        const float v   = WDn * invW10;      // wd/W
                        const float bv  = negb2 * v;
                        const float dd  = fmaf(bv, v, ct2);  // p - s
                        const float tq  = tanh_fast(10.0f * dd);  // MUFU
                        const float qh  = halfF * dd;
                        qv[i] = fmaf(tq, qh, qh);            // F*H(p-s)*(p-s)
                    }
                    out4[kd * NGRP_C + j] =
                        make_float4(qv[0], qv[1], qv[2], qv[3]);
                }
            }
        }
        __syncthreads();
    }
}

extern "C" void kernel_launch(void* const* d_in, const int* in_sizes, int n_in,
                              void* d_out, int out_size) {
    const float* inputs = (const float*)d_in[0];
    const float* wum = (const float*)d_in[1];
    const float* wlm = (const float*)d_in[2];
    const float* wdm = (const float*)d_in[3];
    const float* c   = (const float*)d_in[4];
    const float* bb  = (const float*)d_in[5];
    const float* k1  = (const float*)d_in[6];
    const float* k2  = (const float*)d_in[7];
    const float* k3  = (const float*)d_in[8];
    float* out = (float*)d_out;

    const int B = in_sizes[0] / (T_LEN * 3);

    dim3 block(160);                // 5 warps: A, B, C, D, Loader
    dim3 grid(B / 32);              // 32 rows per block
    xaj_kernel<<<grid, block>>>(inputs, wum, wlm, wdm, c, bb, k1, k2, k3, out, B);
}